// round 2
// baseline (speedup 1.0000x reference)
#include <cuda_runtime.h>
#include <cuda_bf16.h>
#include <math.h>

// Problem constants
#define E_    16
#define H_    1024
#define F_    1024
#define D_    2048
#define R_    16
#define T_    1024
#define TOPK_ 2
#define NSLOT (T_ * TOPK_)   // 2048 total (token,expert) slots
#define SCALING_ 1.0f        // 16.0 / R = 1.0
#define LIMIT_   7.0f
#define ACT_ALPHA_ 1.702f

// ---------------- device scratch (allocation-free: __device__ globals) ------
__device__ int   d_count[E_];
__device__ int   d_off[E_];
__device__ int   d_slot_token[NSLOT];
__device__ int   d_slot_expert[NSLOT];
__device__ float d_slot_w[NSLOT];
__device__ int   d_tok_slot[NSLOT];         // (t,k) -> slot
__device__ float d_xg[(size_t)NSLOT * H_];  // gathered activations  8 MB
__device__ float d_r1[NSLOT * R_];          // lora rank acts, stage1
__device__ float d_g [(size_t)NSLOT * F_];  // glu output            8 MB
__device__ float d_r2[NSLOT * R_];          // lora rank acts, stage2
__device__ float d_y [(size_t)NSLOT * H_];  // down output           8 MB

// ---------------- routing: counts, CSR offsets, slot fill -------------------
__global__ void route_kernel(const int* __restrict__ ridx,
                             const float* __restrict__ rw) {
    __shared__ int cnt[E_], cur[E_], soff[E_ + 1];
    int t = threadIdx.x;  // 1024 threads
    if (t < E_) { cnt[t] = 0; cur[t] = 0; }
    __syncthreads();
    for (int i = t; i < NSLOT; i += blockDim.x)
        atomicAdd(&cnt[ridx[i]], 1);
    __syncthreads();
    if (t == 0) {
        int s = 0;
        for (int e = 0; e < E_; e++) { soff[e] = s; s += cnt[e]; }
        soff[E_] = s;
    }
    __syncthreads();
    for (int i = t; i < NSLOT; i += blockDim.x) {
        int e = ridx[i];
        int slot = soff[e] + atomicAdd(&cur[e], 1);
        d_slot_token[slot]  = i >> 1;
        d_slot_expert[slot] = e;
        d_slot_w[slot]      = rw[i];
        d_tok_slot[i]       = slot;
    }
    if (t < E_) { d_count[t] = cnt[t]; d_off[t] = soff[t]; }
}

// ---------------- gather x rows into slot order ------------------------------
__global__ void gather_kernel(const float* __restrict__ x) {
    int slot = blockIdx.x;
    int tok  = d_slot_token[slot];
    int c    = threadIdx.x * 4;  // 256 threads * 4 = 1024
    *(float4*)&d_xg[(size_t)slot * H_ + c] =
        *(const float4*)&x[(size_t)tok * H_ + c];
}

// ---------------- LoRA rank projection: r[slot][0..15] = src_row . A_e ------
// STAGE1: src = d_xg, dst = d_r1 ; else src = d_g, dst = d_r2
template <bool STAGE1>
__global__ void lora_r_kernel(const float* __restrict__ A) {  // [E,1024,16]
    int slot = blockIdx.x;
    int e    = d_slot_expert[slot];
    const float* Ae   = A + (size_t)e * 1024 * R_;
    const float* srow = (STAGE1 ? d_xg : d_g) + (size_t)slot * 1024;
    float* rout = STAGE1 ? d_r1 : d_r2;
    int tid = threadIdx.x;  // 256
    float acc[R_];
#pragma unroll
    for (int j = 0; j < R_; j++) acc[j] = 0.f;
    for (int k = tid; k < 1024; k += 256) {
        float a = srow[k];
        const float* ar = Ae + k * R_;
#pragma unroll
        for (int j = 0; j < R_; j++) acc[j] += a * ar[j];
    }
#pragma unroll
    for (int o = 16; o > 0; o >>= 1)
#pragma unroll
        for (int j = 0; j < R_; j++)
            acc[j] += __shfl_down_sync(0xffffffffu, acc[j], o);
    __shared__ float wr[8][R_];
    int lane = tid & 31, w = tid >> 5;
    if (lane == 0)
#pragma unroll
        for (int j = 0; j < R_; j++) wr[w][j] = acc[j];
    __syncthreads();
    if (tid < R_) {
        float s = 0.f;
#pragma unroll
        for (int ww = 0; ww < 8; ww++) s += wr[ww][tid];
        rout[slot * R_ + tid] = s * SCALING_;
    }
}

// ---------------- main grouped GEMM (K extended 1024 -> 1040 for LoRA) -----
template <bool STAGE1>
__global__ __launch_bounds__(256)
void moe_gemm_kernel(const float* __restrict__ W,      // [E,1024,N]
                     const float* __restrict__ Blora,  // [E,16,N]
                     const float* __restrict__ bias,   // [E,N]
                     int Ncols) {
    constexpr int BM = 64, BN = 128, BK = 16;
    int e  = blockIdx.z;
    int ne = d_count[e];
    int m0 = blockIdx.y * BM;
    if (m0 >= ne) return;
    int off = d_off[e];
    int n0  = blockIdx.x * BN;

    const float* Asrc = STAGE1 ? d_xg : d_g;   // [NSLOT,1024]
    const float* Rsrc = STAGE1 ? d_r1 : d_r2;  // [NSLOT,16]
    float*       Out  = STAGE1 ? d_g  : d_y;

    __shared__ float As[BM][BK];
    __shared__ float Bs[BK][BN];

    float acc[4][8];
#pragma unroll
    for (int i = 0; i < 4; i++)
#pragma unroll
        for (int j = 0; j < 8; j++) acc[i][j] = 0.f;

    int tid = threadIdx.x;
    int tx = tid & 15;   // col group: 8 cols
    int ty = tid >> 4;   // row group: 4 rows

    const float* Wp = W     + (size_t)e * 1024 * Ncols;
    const float* Bp = Blora + (size_t)e * R_   * Ncols;

    for (int k0 = 0; k0 < 1024 + R_; k0 += BK) {
        bool lora = (k0 >= 1024);
        {
            int row = tid >> 2;
            int kk  = (tid & 3) << 2;
            float4 v = make_float4(0.f, 0.f, 0.f, 0.f);
            if (m0 + row < ne) {
                int slot = off + m0 + row;
                const float* p = lora
                    ? (Rsrc + (size_t)slot * R_ + (k0 - 1024) + kk)
                    : (Asrc + (size_t)slot * 1024 + k0 + kk);
                v = *(const float4*)p;
            }
            *(float4*)&As[row][kk] = v;
        }
#pragma unroll
        for (int it = 0; it < 2; it++) {
            int f4 = tid + it * 256;
            int kk = f4 >> 5;
            int c  = (f4 & 31) << 2;
            const float* p = lora
                ? (Bp + (size_t)(k0 - 1024 + kk) * Ncols + n0 + c)
                : (Wp + (size_t)(k0 + kk) * Ncols + n0 + c);
            *(float4*)&Bs[kk][c] = *(const float4*)p;
        }
        __syncthreads();
#pragma unroll
        for (int kk = 0; kk < BK; kk++) {
            float a[4];
#pragma unroll
            for (int i = 0; i < 4; i++) a[i] = As[ty * 4 + i][kk];
            float4 b0 = *(float4*)&Bs[kk][tx * 8];
            float4 b1 = *(float4*)&Bs[kk][tx * 8 + 4];
            float b[8] = {b0.x, b0.y, b0.z, b0.w, b1.x, b1.y, b1.z, b1.w};
#pragma unroll
            for (int i = 0; i < 4; i++)
#pragma unroll
                for (int j = 0; j < 8; j++)
                    acc[i][j] = fmaf(a[i], b[j], acc[i][j]);
        }
        __syncthreads();
    }

    const float* be = bias + (size_t)e * Ncols;
    int c0 = n0 + tx * 8;
#pragma unroll
    for (int i = 0; i < 4; i++) {
        int m = m0 + ty * 4 + i;
        if (m >= ne) break;
        int slot = off + m;
        float v[8];
#pragma unroll
        for (int j = 0; j < 8; j++) v[j] = acc[i][j] + be[c0 + j];
        if (STAGE1) {
            float4 gout;
            float* go = (float*)&gout;
#pragma unroll
            for (int p = 0; p < 4; p++) {
                float gate = fminf(v[2 * p], LIMIT_);
                float up   = fminf(fmaxf(v[2 * p + 1], -LIMIT_), LIMIT_);
                float glu  = gate / (1.f + expf(-ACT_ALPHA_ * gate));
                go[p] = (up + 1.f) * glu;
            }
            *(float4*)&Out[(size_t)slot * F_ + (c0 >> 1)] = gout;
        } else {
            *(float4*)&Out[(size_t)slot * H_ + c0] =
                make_float4(v[0], v[1], v[2], v[3]);
            *(float4*)&Out[(size_t)slot * H_ + c0 + 4] =
                make_float4(v[4], v[5], v[6], v[7]);
        }
    }
}

// ---------------- final combine: out[t] = w0*y[s0] + w1*y[s1] ---------------
__global__ void combine_kernel(float* __restrict__ out) {
    int t  = blockIdx.x;
    int s0 = d_tok_slot[2 * t];
    int s1 = d_tok_slot[2 * t + 1];
    float w0 = d_slot_w[s0];
    float w1 = d_slot_w[s1];
    int c = threadIdx.x * 4;
    float4 a = *(float4*)&d_y[(size_t)s0 * H_ + c];
    float4 b = *(float4*)&d_y[(size_t)s1 * H_ + c];
    float4 o;
    o.x = w0 * a.x + w1 * b.x;
    o.y = w0 * a.y + w1 * b.y;
    o.z = w0 * a.z + w1 * b.z;
    o.w = w0 * a.w + w1 * b.w;
    *(float4*)&out[(size_t)t * H_ + c] = o;
}

// ---------------- launch: kernel launches ONLY ------------------------------
extern "C" void kernel_launch(void* const* d_in, const int* in_sizes, int n_in,
                              void* d_out, int out_size) {
    const float* x     = (const float*)d_in[0];   // [2,512,1024]
    const int*   ridx  = (const int*)  d_in[1];   // [1024,2]
    const float* rw    = (const float*)d_in[2];   // [1024,2]
    const float* w_gu  = (const float*)d_in[3];   // [16,1024,2048]
    const float* b_gu  = (const float*)d_in[4];   // [16,2048]
    const float* w_dn  = (const float*)d_in[5];   // [16,1024,1024]
    const float* b_dn  = (const float*)d_in[6];   // [16,1024]
    const float* la_gu = (const float*)d_in[7];   // [16,1024,16]
    const float* lb_gu = (const float*)d_in[8];   // [16,16,2048]
    const float* la_dn = (const float*)d_in[9];   // [16,1024,16]
    const float* lb_dn = (const float*)d_in[10];  // [16,16,1024]
    float* out = (float*)d_out;

    route_kernel<<<1, 1024>>>(ridx, rw);
    gather_kernel<<<NSLOT, 256>>>(x);

    lora_r_kernel<true ><<<NSLOT, 256>>>(la_gu);
    dim3 grid1(D_ / 128, NSLOT / 64, E_);
    moe_gemm_kernel<true ><<<grid1, 256>>>(w_gu, lb_gu, b_gu, D_);

    lora_r_kernel<false><<<NSLOT, 256>>>(la_dn);
    dim3 grid2(H_ / 128, NSLOT / 64, E_);
    moe_gemm_kernel<false><<<grid2, 256>>>(w_dn, lb_dn, b_dn, H_);

    combine_kernel<<<T_, 256>>>(out);
}

// round 4
// speedup vs baseline: 2.5244x; 2.5244x over previous
#include <cuda_runtime.h>
#include <cuda_bf16.h>
#include <math.h>
#include <stdint.h>

// Problem constants
#define E_    16
#define H_    1024
#define D_    2048
#define R_    16
#define T_    1024
#define NSLOT 2048
#define LIMIT_   7.0f
#define ACT_ALPHA_ 1.702f

// ---------------- device scratch ------------------------------------------
__device__ int   d_count[E_];
__device__ int   d_off[E_];
__device__ int   d_slot_token[NSLOT];
__device__ int   d_slot_expert[NSLOT];
__device__ float d_slot_w[NSLOT];
__device__ int   d_tok_slot[NSLOT];
__device__ float d_xg[(size_t)NSLOT * H_];
__device__ float d_r1[NSLOT * R_];
__device__ float d_g [(size_t)NSLOT * 1024];
__device__ float d_r2[NSLOT * R_];
__device__ float d_y [(size_t)NSLOT * H_];

// ---------------- routing ---------------------------------------------------
__global__ void route_kernel(const int* __restrict__ ridx,
                             const float* __restrict__ rw) {
    __shared__ int cnt[E_], cur[E_], soff[E_ + 1];
    int t = threadIdx.x;
    if (t < E_) { cnt[t] = 0; cur[t] = 0; }
    __syncthreads();
    for (int i = t; i < NSLOT; i += blockDim.x)
        atomicAdd(&cnt[ridx[i]], 1);
    __syncthreads();
    if (t == 0) {
        int s = 0;
        for (int e = 0; e < E_; e++) { soff[e] = s; s += cnt[e]; }
        soff[E_] = s;
    }
    __syncthreads();
    for (int i = t; i < NSLOT; i += blockDim.x) {
        int e = ridx[i];
        int slot = soff[e] + atomicAdd(&cur[e], 1);
        d_slot_token[slot]  = i >> 1;
        d_slot_expert[slot] = e;
        d_slot_w[slot]      = rw[i];
        d_tok_slot[i]       = slot;
    }
    if (t < E_) { d_count[t] = cnt[t]; d_off[t] = soff[t]; }
}

// ---------------- gather -----------------------------------------------------
__global__ void gather_kernel(const float* __restrict__ x) {
    int slot = blockIdx.x;
    int tok  = d_slot_token[slot];
    int c    = threadIdx.x * 4;
    *(float4*)&d_xg[(size_t)slot * H_ + c] =
        *(const float4*)&x[(size_t)tok * H_ + c];
}

// ---------------- LoRA rank projection --------------------------------------
template <bool STAGE1>
__global__ void lora_r_kernel(const float* __restrict__ A) {  // [E,1024,16]
    int slot = blockIdx.x;
    int e    = d_slot_expert[slot];
    const float* Ae   = A + (size_t)e * 1024 * R_;
    const float* srow = (STAGE1 ? d_xg : d_g) + (size_t)slot * 1024;
    float* rout = STAGE1 ? d_r1 : d_r2;
    int tid = threadIdx.x;  // 256
    float acc[R_];
#pragma unroll
    for (int j = 0; j < R_; j++) acc[j] = 0.f;
    for (int k = tid; k < 1024; k += 256) {
        float a = srow[k];
        const float* ar = Ae + k * R_;
#pragma unroll
        for (int j = 0; j < R_; j++) acc[j] += a * ar[j];
    }
#pragma unroll
    for (int o = 16; o > 0; o >>= 1)
#pragma unroll
        for (int j = 0; j < R_; j++)
            acc[j] += __shfl_down_sync(0xffffffffu, acc[j], o);
    __shared__ float wr[8][R_];
    int lane = tid & 31, w = tid >> 5;
    if (lane == 0)
#pragma unroll
        for (int j = 0; j < R_; j++) wr[w][j] = acc[j];
    __syncthreads();
    if (tid < R_) {
        float s = 0.f;
#pragma unroll
        for (int ww = 0; ww < 8; ww++) s += wr[ww][tid];
        rout[slot * R_ + tid] = s;  // SCALING = 16/16 = 1
    }
}

// ================= mma.sync helpers =========================================
__device__ __forceinline__ uint32_t smem_u32(const void* p) {
    return (uint32_t)__cvta_generic_to_shared(p);
}

__device__ __forceinline__ void ldsm4(uint32_t* r, uint32_t addr) {
    asm volatile("ldmatrix.sync.aligned.m8n8.x4.shared.b16 {%0,%1,%2,%3}, [%4];"
                 : "=r"(r[0]), "=r"(r[1]), "=r"(r[2]), "=r"(r[3]) : "r"(addr));
}
__device__ __forceinline__ void ldsm4t(uint32_t* r, uint32_t addr) {
    asm volatile("ldmatrix.sync.aligned.m8n8.x4.trans.shared.b16 {%0,%1,%2,%3}, [%4];"
                 : "=r"(r[0]), "=r"(r[1]), "=r"(r[2]), "=r"(r[3]) : "r"(addr));
}
__device__ __forceinline__ void mma16816(float* d, const uint32_t* a,
                                         const uint32_t* b) {
    asm volatile(
        "mma.sync.aligned.m16n8k16.row.col.f32.bf16.bf16.f32 "
        "{%0,%1,%2,%3}, {%4,%5,%6,%7}, {%8,%9}, {%0,%1,%2,%3};"
        : "+f"(d[0]), "+f"(d[1]), "+f"(d[2]), "+f"(d[3])
        : "r"(a[0]), "r"(a[1]), "r"(a[2]), "r"(a[3]), "r"(b[0]), "r"(b[1]));
}

// split fp32x4 -> bf16 hi / residual-lo packed pairs
__device__ __forceinline__ void cvt4(const float4 f, uint2& hi, uint2& lo) {
    __nv_bfloat16 h0 = __float2bfloat16(f.x), h1 = __float2bfloat16(f.y),
                  h2 = __float2bfloat16(f.z), h3 = __float2bfloat16(f.w);
    __nv_bfloat16 l0 = __float2bfloat16(f.x - __bfloat162float(h0)),
                  l1 = __float2bfloat16(f.y - __bfloat162float(h1)),
                  l2 = __float2bfloat16(f.z - __bfloat162float(h2)),
                  l3 = __float2bfloat16(f.w - __bfloat162float(h3));
    hi.x = ((uint32_t)__bfloat16_as_ushort(h1) << 16) | __bfloat16_as_ushort(h0);
    hi.y = ((uint32_t)__bfloat16_as_ushort(h3) << 16) | __bfloat16_as_ushort(h2);
    lo.x = ((uint32_t)__bfloat16_as_ushort(l1) << 16) | __bfloat16_as_ushort(l0);
    lo.y = ((uint32_t)__bfloat16_as_ushort(l3) << 16) | __bfloat16_as_ushort(l2);
}

// SMEM layout (static, 20480 B):
//   AH [128 rows x 48B] @ 0      AL @ 6144
//   BH [16 rows x 256B] @ 12288  BL @ 16384
#define SM_AH 0
#define SM_AL 6144
#define SM_BH 12288
#define SM_BL 16384

// ================= grouped GEMM via mma.sync (bf16 3-product fp32-emu) ======
// STAGE1: g = act(xg @ Wgu + r1 @ LBgu + bias)   Ncols=2048
// STAGE2: y = g  @ Wdn + r2 @ LBdn + bias        Ncols=1024
// CTA tile 128x128, BK=16; K-loop: 64 main iters + 1 LoRA iter (rank 16).
template <bool STAGE1>
__global__ __launch_bounds__(256)
void moe_mma_kernel(const float* __restrict__ W,    // [E,1024,Ncols]
                    const float* __restrict__ LB,   // [E,16,Ncols]
                    const float* __restrict__ bias, // [E,Ncols]
                    int Ncols) {
    const int e  = blockIdx.z;
    const int ne = d_count[e];
    const int m0 = blockIdx.y * 128;
    if (m0 >= ne) return;
    const int off = d_off[e];
    const int n0  = blockIdx.x * 128;
    const float* Asrc = STAGE1 ? d_xg : d_g;
    const float* Rsrc = STAGE1 ? d_r1 : d_r2;
    float*       Out  = STAGE1 ? d_g  : d_y;

    __shared__ __align__(16) char sm[20480];
    const uint32_t sb = smem_u32(sm);

    const int tid  = threadIdx.x;
    const int lane = tid & 31;
    const int wid  = tid >> 5;
    const int wm   = wid >> 2;       // 0..1 (64 rows each)
    const int wn   = wid & 3;        // 0..3 (32 cols each)

    // gmem load mapping: 512 float4 per tile, 2 per thread
    const int f4base = tid * 2;

    float acc[4][4][4];
#pragma unroll
    for (int i = 0; i < 4; i++)
#pragma unroll
        for (int j = 0; j < 4; j++)
#pragma unroll
            for (int q = 0; q < 4; q++) acc[i][j][q] = 0.f;

    float4 pa[2], pb[2];

    auto loadA = [&](int it, int i) -> float4 {
        int f4 = f4base + i;
        int row = f4 >> 2, kc = f4 & 3;
        if (m0 + row >= ne) return make_float4(0.f, 0.f, 0.f, 0.f);
        size_t slot = (size_t)(off + m0 + row);
        const float* p = (it < 64)
            ? Asrc + slot * 1024 + it * 16 + kc * 4
            : Rsrc + slot * R_ + kc * 4;
        return *(const float4*)p;
    };
    auto loadB = [&](int it, int i) -> float4 {
        int f4 = f4base + i;
        int krow = f4 >> 5, nchunk = f4 & 31;
        const float* p = (it < 64)
            ? W  + ((size_t)e * 1024 + it * 16 + krow) * Ncols + n0 + nchunk * 4
            : LB + ((size_t)e * R_ + krow) * Ncols + n0 + nchunk * 4;
        return *(const float4*)p;
    };

    pa[0] = loadA(0, 0); pa[1] = loadA(0, 1);
    pb[0] = loadB(0, 0); pb[1] = loadB(0, 1);

    for (int it = 0; it < 65; ++it) {
        __syncthreads();  // all warps done reading previous tiles
        // ---- convert + store to SMEM ----
#pragma unroll
        for (int i = 0; i < 2; i++) {
            int f4 = f4base + i;
            {
                int row = f4 >> 2, kc = f4 & 3;
                uint2 hi, lo; cvt4(pa[i], hi, lo);
                int ofs = row * 48 + kc * 8;
                *(uint2*)(sm + SM_AH + ofs) = hi;
                *(uint2*)(sm + SM_AL + ofs) = lo;
            }
            {
                int krow = f4 >> 5, nchunk = f4 & 31;
                uint2 hi, lo; cvt4(pb[i], hi, lo);
                int ofs = krow * 256 + (((nchunk >> 1) ^ (krow & 7)) << 4)
                        + (nchunk & 1) * 8;
                *(uint2*)(sm + SM_BH + ofs) = hi;
                *(uint2*)(sm + SM_BL + ofs) = lo;
            }
        }
        __syncthreads();

        // ---- prefetch next tile (overlaps with MMA below) ----
        if (it < 64) {
            pa[0] = loadA(it + 1, 0); pa[1] = loadA(it + 1, 1);
            pb[0] = loadB(it + 1, 0); pb[1] = loadB(it + 1, 1);
        }

        // ---- B fragments: 2x ldmatrix.x4.trans per matrix (16 n each) ----
        uint32_t bh[2][4], bl[2][4];
        {
            int k = ((lane >> 3) & 1) * 8 + (lane & 7);
            int cbase = (lane >> 4);
#pragma unroll
            for (int g = 0; g < 2; g++) {
                int c = (wn * 2 + g) * 2 + cbase;
                uint32_t ad = sb + SM_BH + k * 256 + ((c ^ (k & 7)) << 4);
                ldsm4t(bh[g], ad);
                ldsm4t(bl[g], ad + (SM_BL - SM_BH));
            }
        }
        // ---- A fragments + MMAs ----
#pragma unroll
        for (int mt = 0; mt < 4; mt++) {
            uint32_t ah[4], al[4];
            int m = wm * 64 + mt * 16 + (lane & 15);
            uint32_t ad = sb + SM_AH + m * 48 + (lane >> 4) * 16;
            ldsm4(ah, ad);
            ldsm4(al, ad + (SM_AL - SM_AH));
#pragma unroll
            for (int nt = 0; nt < 4; nt++) {
                const uint32_t* pbh = &bh[nt >> 1][(nt & 1) * 2];
                const uint32_t* pbl = &bl[nt >> 1][(nt & 1) * 2];
                float* c = acc[mt][nt];
                mma16816(c, ah, pbh);
                mma16816(c, ah, pbl);
                mma16816(c, al, pbh);
            }
        }
    }

    // ---- epilogue ----
    const float* be = bias + (size_t)e * Ncols + n0;
    float bb[4][2];
#pragma unroll
    for (int nt = 0; nt < 4; nt++) {
        int col = wn * 32 + nt * 8 + (lane & 3) * 2;
        bb[nt][0] = __ldg(be + col);
        bb[nt][1] = __ldg(be + col + 1);
    }
#pragma unroll
    for (int mt = 0; mt < 4; mt++) {
        int rbase = m0 + wm * 64 + mt * 16 + (lane >> 2);
#pragma unroll
        for (int half = 0; half < 2; half++) {
            int r = rbase + half * 8;
            if (r >= ne) continue;
            size_t slot = (size_t)(off + r);
#pragma unroll
            for (int nt = 0; nt < 4; nt++) {
                float c0 = acc[mt][nt][half * 2]     + bb[nt][0];
                float c1 = acc[mt][nt][half * 2 + 1] + bb[nt][1];
                int col = wn * 32 + nt * 8 + (lane & 3) * 2;
                if (STAGE1) {
                    float gate = fminf(c0, LIMIT_);
                    float up   = fminf(fmaxf(c1, -LIMIT_), LIMIT_);
                    float glu  = gate / (1.f + expf(-ACT_ALPHA_ * gate));
                    Out[slot * 1024 + (n0 >> 1) + (col >> 1)] = (up + 1.f) * glu;
                } else {
                    *(float2*)&Out[slot * 1024 + n0 + col] = make_float2(c0, c1);
                }
            }
        }
    }
}

// ---------------- final combine ---------------------------------------------
__global__ void combine_kernel(float* __restrict__ out) {
    int t  = blockIdx.x;
    int s0 = d_tok_slot[2 * t];
    int s1 = d_tok_slot[2 * t + 1];
    float w0 = d_slot_w[s0];
    float w1 = d_slot_w[s1];
    int c = threadIdx.x * 4;
    float4 a = *(float4*)&d_y[(size_t)s0 * H_ + c];
    float4 b = *(float4*)&d_y[(size_t)s1 * H_ + c];
    float4 o;
    o.x = w0 * a.x + w1 * b.x;
    o.y = w0 * a.y + w1 * b.y;
    o.z = w0 * a.z + w1 * b.z;
    o.w = w0 * a.w + w1 * b.w;
    *(float4*)&out[(size_t)t * H_ + c] = o;
}

// ---------------- launch: kernel launches ONLY ------------------------------
extern "C" void kernel_launch(void* const* d_in, const int* in_sizes, int n_in,
                              void* d_out, int out_size) {
    const float* x     = (const float*)d_in[0];
    const int*   ridx  = (const int*)  d_in[1];
    const float* rw    = (const float*)d_in[2];
    const float* w_gu  = (const float*)d_in[3];
    const float* b_gu  = (const float*)d_in[4];
    const float* w_dn  = (const float*)d_in[5];
    const float* b_dn  = (const float*)d_in[6];
    const float* la_gu = (const float*)d_in[7];
    const float* lb_gu = (const float*)d_in[8];
    const float* la_dn = (const float*)d_in[9];
    const float* lb_dn = (const float*)d_in[10];
    float* out = (float*)d_out;

    route_kernel<<<1, 1024>>>(ridx, rw);
    gather_kernel<<<NSLOT, 256>>>(x);

    lora_r_kernel<true ><<<NSLOT, 256>>>(la_gu);
    moe_mma_kernel<true ><<<dim3(D_ / 128, 16, E_), 256>>>(w_gu, lb_gu, b_gu, D_);

    lora_r_kernel<false><<<NSLOT, 256>>>(la_dn);
    moe_mma_kernel<false><<<dim3(H_ / 128, 16, E_), 256>>>(w_dn, lb_dn, b_dn, H_);

    combine_kernel<<<T_, 256>>>(out);
}

// round 6
// speedup vs baseline: 3.3213x; 1.3157x over previous
#include <cuda_runtime.h>
#include <cuda_bf16.h>
#include <math.h>
#include <stdint.h>

// Problem constants
#define E_    16
#define H_    1024
#define D_    2048
#define R_    16
#define T_    1024
#define NSLOT 2048
#define LIMIT_   7.0f
#define ACT_ALPHA_ 1.702f

// ---------------- device scratch ------------------------------------------
__device__ int   d_count[E_];
__device__ int   d_off[E_];
__device__ int   d_slot_token[NSLOT];
__device__ int   d_slot_expert[NSLOT];
__device__ float d_slot_w[NSLOT];
__device__ float d_r1[NSLOT * R_];
__device__ float d_g [(size_t)NSLOT * 1024];
__device__ float d_r2[NSLOT * R_];

// ---------------- routing ---------------------------------------------------
__global__ void route_kernel(const int* __restrict__ ridx,
                             const float* __restrict__ rw) {
    __shared__ int cnt[E_], cur[E_], soff[E_ + 1];
    int t = threadIdx.x;
    if (t < E_) { cnt[t] = 0; cur[t] = 0; }
    __syncthreads();
    for (int i = t; i < NSLOT; i += blockDim.x)
        atomicAdd(&cnt[ridx[i]], 1);
    __syncthreads();
    if (t == 0) {
        int s = 0;
        for (int e = 0; e < E_; e++) { soff[e] = s; s += cnt[e]; }
        soff[E_] = s;
    }
    __syncthreads();
    for (int i = t; i < NSLOT; i += blockDim.x) {
        int e = ridx[i];
        int slot = soff[e] + atomicAdd(&cur[e], 1);
        d_slot_token[slot]  = i >> 1;
        d_slot_expert[slot] = e;
        d_slot_w[slot]      = rw[i];
    }
    if (t < E_) { d_count[t] = cnt[t]; d_off[t] = soff[t]; }
}

// ---------------- zero output (atomically accumulated later) -----------------
__global__ void zero_out_kernel(float* __restrict__ out) {
    int i = blockIdx.x * 256 + threadIdx.x;
    *(float4*)&out[(size_t)i * 4] = make_float4(0.f, 0.f, 0.f, 0.f);
}

// ---------------- LoRA rank projection --------------------------------------
// STAGE1: src row = x[token(slot)]; STAGE2: src row = d_g[slot]
template <bool STAGE1>
__global__ void lora_r_kernel(const float* __restrict__ xsrc,
                              const float* __restrict__ A) {  // [E,1024,16]
    int slot = blockIdx.x;
    int e    = d_slot_expert[slot];
    const float* Ae   = A + (size_t)e * 1024 * R_;
    const float* srow = STAGE1 ? (xsrc + (size_t)d_slot_token[slot] * 1024)
                               : (d_g + (size_t)slot * 1024);
    float* rout = STAGE1 ? d_r1 : d_r2;
    int tid = threadIdx.x;  // 256
    float acc[R_];
#pragma unroll
    for (int j = 0; j < R_; j++) acc[j] = 0.f;
    for (int k = tid; k < 1024; k += 256) {
        float a = srow[k];
        const float4* ar = (const float4*)(Ae + k * R_);
#pragma unroll
        for (int q = 0; q < 4; q++) {
            float4 v = __ldg(ar + q);
            acc[q * 4]     += a * v.x;
            acc[q * 4 + 1] += a * v.y;
            acc[q * 4 + 2] += a * v.z;
            acc[q * 4 + 3] += a * v.w;
        }
    }
#pragma unroll
    for (int o = 16; o > 0; o >>= 1)
#pragma unroll
        for (int j = 0; j < R_; j++)
            acc[j] += __shfl_down_sync(0xffffffffu, acc[j], o);
    __shared__ float wr[8][R_];
    int lane = tid & 31, w = tid >> 5;
    if (lane == 0)
#pragma unroll
        for (int j = 0; j < R_; j++) wr[w][j] = acc[j];
    __syncthreads();
    if (tid < R_) {
        float s = 0.f;
#pragma unroll
        for (int ww = 0; ww < 8; ww++) s += wr[ww][tid];
        rout[slot * R_ + tid] = s;  // SCALING = 16/16 = 1
    }
}

// ================= mma.sync helpers =========================================
__device__ __forceinline__ uint32_t smem_u32(const void* p) {
    return (uint32_t)__cvta_generic_to_shared(p);
}
__device__ __forceinline__ void ldsm4(uint32_t* r, uint32_t addr) {
    asm volatile("ldmatrix.sync.aligned.m8n8.x4.shared.b16 {%0,%1,%2,%3}, [%4];"
                 : "=r"(r[0]), "=r"(r[1]), "=r"(r[2]), "=r"(r[3]) : "r"(addr));
}
__device__ __forceinline__ void ldsm4t(uint32_t* r, uint32_t addr) {
    asm volatile("ldmatrix.sync.aligned.m8n8.x4.trans.shared.b16 {%0,%1,%2,%3}, [%4];"
                 : "=r"(r[0]), "=r"(r[1]), "=r"(r[2]), "=r"(r[3]) : "r"(addr));
}
__device__ __forceinline__ void mma16816(float* d, const uint32_t* a,
                                         const uint32_t* b) {
    asm volatile(
        "mma.sync.aligned.m16n8k16.row.col.f32.bf16.bf16.f32 "
        "{%0,%1,%2,%3}, {%4,%5,%6,%7}, {%8,%9}, {%0,%1,%2,%3};"
        : "+f"(d[0]), "+f"(d[1]), "+f"(d[2]), "+f"(d[3])
        : "r"(a[0]), "r"(a[1]), "r"(a[2]), "r"(a[3]), "r"(b[0]), "r"(b[1]));
}
// split fp32x4 -> bf16 hi / residual-lo packed pairs
__device__ __forceinline__ void cvt4(const float4 f, uint2& hi, uint2& lo) {
    __nv_bfloat16 h0 = __float2bfloat16(f.x), h1 = __float2bfloat16(f.y),
                  h2 = __float2bfloat16(f.z), h3 = __float2bfloat16(f.w);
    __nv_bfloat16 l0 = __float2bfloat16(f.x - __bfloat162float(h0)),
                  l1 = __float2bfloat16(f.y - __bfloat162float(h1)),
                  l2 = __float2bfloat16(f.z - __bfloat162float(h2)),
                  l3 = __float2bfloat16(f.w - __bfloat162float(h3));
    hi.x = ((uint32_t)__bfloat16_as_ushort(h1) << 16) | __bfloat16_as_ushort(h0);
    hi.y = ((uint32_t)__bfloat16_as_ushort(h3) << 16) | __bfloat16_as_ushort(h2);
    lo.x = ((uint32_t)__bfloat16_as_ushort(l1) << 16) | __bfloat16_as_ushort(l0);
    lo.y = ((uint32_t)__bfloat16_as_ushort(l3) << 16) | __bfloat16_as_ushort(l2);
}

// SMEM layout (static, 40960 B), double-buffered:
//   A[stage][hi/lo]: 128 rows x 48B   B[stage][hi/lo]: 16 rows x 256B
#define SM_A(s, l) ((s) * 12288 + (l) * 6144)
#define SM_B(s, l) (24576 + (s) * 8192 + (l) * 4096)

// ================= grouped GEMM via mma.sync (bf16 3-product fp32-emu) ======
// STAGE1: d_g = act(x[tok] @ Wgu + r1 @ LBgu + bias)    Ncols=2048
// STAGE2: out += w * (d_g @ Wdn + r2 @ LBdn + bias)     Ncols=1024, atomics
// CTA tile 128x128, BK=16; K-loop: 64 main iters + 1 LoRA iter (rank 16).
template <bool STAGE1>
__global__ __launch_bounds__(256, 2)
void moe_mma_kernel(const float* __restrict__ xsrc,  // x (stage1) / unused
                    const float* __restrict__ W,     // [E,1024,Ncols]
                    const float* __restrict__ LB,    // [E,16,Ncols]
                    const float* __restrict__ bias,  // [E,Ncols]
                    float* __restrict__ Out,         // final out (stage2)
                    int Ncols) {
    const int e  = blockIdx.z;
    const int ne = d_count[e];
    const int off = d_off[e];
    const int n0  = blockIdx.x * 128;
    const float* Rsrc = STAGE1 ? d_r1 : d_r2;
    float* Outp = STAGE1 ? d_g : Out;   // FIX: stage1 writes d_g internally

    __shared__ __align__(16) char sm[40960];
    const uint32_t sb = smem_u32(sm);

    const int tid  = threadIdx.x;
    const int lane = tid & 31;
    const int wid  = tid >> 5;
    const int wm   = wid >> 2;       // 0..1 (64 rows)
    const int wn   = wid & 3;        // 0..3 (32 cols)

    // fixed per-thread load mapping
    const int arow = tid >> 1;            // 0..127 (one row per thread)
    const int ac0  = (tid & 1) * 8;       // element offset 0 or 8
    const int krow = tid >> 4;            // 0..15
    const int nch0 = (tid & 15) * 2;      // even float4-chunk
    const int bchunk = ((nch0 >> 1) ^ (krow & 7)) << 4;
    const float* bptr  = W  + ((size_t)e * 1024 + krow) * Ncols + n0 + nch0 * 4;
    const float* lbptr = LB + ((size_t)e * R_   + krow) * Ncols + n0 + nch0 * 4;

    for (int mb = blockIdx.y; mb * 128 < ne; mb += 4) {
        const int m0 = mb * 128;
        const bool avalid = (m0 + arow) < ne;
        const int aslot = off + m0 + arow;
        const float* aptr = nullptr;
        const float* rptr = nullptr;
        if (avalid) {
            aptr = STAGE1 ? (xsrc + (size_t)d_slot_token[aslot] * 1024)
                          : (d_g + (size_t)aslot * 1024);
            rptr = Rsrc + (size_t)aslot * R_;
        }

        float acc[4][4][4];
#pragma unroll
        for (int i = 0; i < 4; i++)
#pragma unroll
            for (int j = 0; j < 4; j++)
#pragma unroll
                for (int q = 0; q < 4; q++) acc[i][j][q] = 0.f;

        float4 pa0, pa1, pb0, pb1;
        auto loadtile = [&](int it) {
            if (it < 64) {
                if (avalid) {
                    pa0 = __ldg((const float4*)(aptr + it * 16 + ac0));
                    pa1 = __ldg((const float4*)(aptr + it * 16 + ac0 + 4));
                } else { pa0 = pa1 = make_float4(0.f, 0.f, 0.f, 0.f); }
                pb0 = __ldg((const float4*)(bptr + (size_t)it * 16 * Ncols));
                pb1 = __ldg((const float4*)(bptr + (size_t)it * 16 * Ncols + 4));
            } else {
                if (avalid) {
                    pa0 = __ldg((const float4*)(rptr + ac0));
                    pa1 = __ldg((const float4*)(rptr + ac0 + 4));
                } else { pa0 = pa1 = make_float4(0.f, 0.f, 0.f, 0.f); }
                pb0 = __ldg((const float4*)lbptr);
                pb1 = __ldg((const float4*)(lbptr + 4));
            }
        };
        auto storetile = [&](int s) {
            uint2 h0, l0, h1, l1;
            cvt4(pa0, h0, l0); cvt4(pa1, h1, l1);
            int aofs = arow * 48 + (tid & 1) * 16;
            *(uint4*)(sm + SM_A(s, 0) + aofs) = make_uint4(h0.x, h0.y, h1.x, h1.y);
            *(uint4*)(sm + SM_A(s, 1) + aofs) = make_uint4(l0.x, l0.y, l1.x, l1.y);
            cvt4(pb0, h0, l0); cvt4(pb1, h1, l1);
            int bofs = krow * 256 + bchunk;
            *(uint4*)(sm + SM_B(s, 0) + bofs) = make_uint4(h0.x, h0.y, h1.x, h1.y);
            *(uint4*)(sm + SM_B(s, 1) + bofs) = make_uint4(l0.x, l0.y, l1.x, l1.y);
        };

        loadtile(0);
        storetile(0);
        __syncthreads();
        int s = 0;
        for (int it = 0; it <= 64; ++it) {
            if (it < 64) loadtile(it + 1);   // prefetch (hidden under MMAs)

            // ---- B fragments ----
            uint32_t bh[2][4], bl[2][4];
            {
                int k = ((lane >> 3) & 1) * 8 + (lane & 7);
                int cbase = (lane >> 4);
#pragma unroll
                for (int g = 0; g < 2; g++) {
                    int c = (wn * 2 + g) * 2 + cbase;
                    uint32_t ad = sb + SM_B(s, 0) + k * 256 + ((c ^ (k & 7)) << 4);
                    ldsm4t(bh[g], ad);
                    ldsm4t(bl[g], ad + 4096);
                }
            }
            // ---- A fragments + MMAs ----
#pragma unroll
            for (int mt = 0; mt < 4; mt++) {
                uint32_t ah[4], al[4];
                int m = wm * 64 + mt * 16 + (lane & 15);
                uint32_t ad = sb + SM_A(s, 0) + m * 48 + (lane >> 4) * 16;
                ldsm4(ah, ad);
                ldsm4(al, ad + 6144);
#pragma unroll
                for (int nt = 0; nt < 4; nt++) {
                    const uint32_t* pbh = &bh[nt >> 1][(nt & 1) * 2];
                    const uint32_t* pbl = &bl[nt >> 1][(nt & 1) * 2];
                    float* c = acc[mt][nt];
                    mma16816(c, ah, pbh);
                    mma16816(c, ah, pbl);
                    mma16816(c, al, pbh);
                }
            }
            if (it < 64) storetile(s ^ 1);
            __syncthreads();
            s ^= 1;
        }

        // ---- epilogue ----
        const float* be = bias + (size_t)e * Ncols + n0;
        float bb[4][2];
#pragma unroll
        for (int nt = 0; nt < 4; nt++) {
            int col = wn * 32 + nt * 8 + (lane & 3) * 2;
            bb[nt][0] = __ldg(be + col);
            bb[nt][1] = __ldg(be + col + 1);
        }
#pragma unroll
        for (int mt = 0; mt < 4; mt++) {
            int rbase = m0 + wm * 64 + mt * 16 + (lane >> 2);
#pragma unroll
            for (int half = 0; half < 2; half++) {
                int r = rbase + half * 8;
                if (r >= ne) continue;
                int slot = off + r;
                if (STAGE1) {
                    size_t orow = (size_t)slot * 1024 + (n0 >> 1);
#pragma unroll
                    for (int nt = 0; nt < 4; nt++) {
                        float c0 = acc[mt][nt][half * 2]     + bb[nt][0];
                        float c1 = acc[mt][nt][half * 2 + 1] + bb[nt][1];
                        int col = wn * 32 + nt * 8 + (lane & 3) * 2;
                        float gate = fminf(c0, LIMIT_);
                        float up   = fminf(fmaxf(c1, -LIMIT_), LIMIT_);
                        float glu  = gate / (1.f + expf(-ACT_ALPHA_ * gate));
                        Outp[orow + (col >> 1)] = (up + 1.f) * glu;
                    }
                } else {
                    float wgt = d_slot_w[slot];
                    size_t orow = (size_t)d_slot_token[slot] * 1024 + n0;
#pragma unroll
                    for (int nt = 0; nt < 4; nt++) {
                        float c0 = acc[mt][nt][half * 2]     + bb[nt][0];
                        float c1 = acc[mt][nt][half * 2 + 1] + bb[nt][1];
                        int col = wn * 32 + nt * 8 + (lane & 3) * 2;
                        atomicAdd(Outp + orow + col,     wgt * c0);
                        atomicAdd(Outp + orow + col + 1, wgt * c1);
                    }
                }
            }
        }
        __syncthreads();  // smem safe for next m-block
    }
}

// ---------------- launch: kernel launches ONLY ------------------------------
extern "C" void kernel_launch(void* const* d_in, const int* in_sizes, int n_in,
                              void* d_out, int out_size) {
    const float* x     = (const float*)d_in[0];
    const int*   ridx  = (const int*)  d_in[1];
    const float* rw    = (const float*)d_in[2];
    const float* w_gu  = (const float*)d_in[3];
    const float* b_gu  = (const float*)d_in[4];
    const float* w_dn  = (const float*)d_in[5];
    const float* b_dn  = (const float*)d_in[6];
    const float* la_gu = (const float*)d_in[7];
    const float* lb_gu = (const float*)d_in[8];
    const float* la_dn = (const float*)d_in[9];
    const float* lb_dn = (const float*)d_in[10];
    float* out = (float*)d_out;

    route_kernel<<<1, 1024>>>(ridx, rw);
    zero_out_kernel<<<T_ * H_ / 1024, 256>>>(out);

    lora_r_kernel<true ><<<NSLOT, 256>>>(x, la_gu);
    moe_mma_kernel<true ><<<dim3(D_ / 128, 4, E_), 256>>>(x, w_gu, lb_gu, b_gu,
                                                          nullptr, D_);
    lora_r_kernel<false><<<NSLOT, 256>>>(x, la_dn);
    moe_mma_kernel<false><<<dim3(H_ / 128, 4, E_), 256>>>(x, w_dn, lb_dn, b_dn,
                                                          out, H_);
}

// round 7
// speedup vs baseline: 4.8129x; 1.4491x over previous
#include <cuda_runtime.h>
#include <cuda_bf16.h>
#include <cuda_fp16.h>
#include <math.h>
#include <stdint.h>

// Problem constants
#define E_    16
#define H_    1024
#define D_    2048
#define R_    16
#define T_    1024
#define NSLOT 2048
#define LIMIT_   7.0f
#define ACT_ALPHA_ 1.702f

// ---------------- device scratch ------------------------------------------
__device__ int   d_count[E_];
__device__ int   d_off[E_];
__device__ int   d_slot_token[NSLOT];
__device__ int   d_slot_expert[NSLOT];
__device__ float d_slot_w[NSLOT];
__device__ float d_r1[NSLOT * R_];
__device__ float d_g [(size_t)NSLOT * 1024];
__device__ float d_r2[NSLOT * R_];

// ---------------- routing ---------------------------------------------------
__global__ void route_kernel(const int* __restrict__ ridx,
                             const float* __restrict__ rw) {
    __shared__ int cnt[E_], cur[E_], soff[E_ + 1];
    int t = threadIdx.x;
    if (t < E_) { cnt[t] = 0; cur[t] = 0; }
    __syncthreads();
    for (int i = t; i < NSLOT; i += blockDim.x)
        atomicAdd(&cnt[ridx[i]], 1);
    __syncthreads();
    if (t == 0) {
        int s = 0;
        for (int e = 0; e < E_; e++) { soff[e] = s; s += cnt[e]; }
        soff[E_] = s;
    }
    __syncthreads();
    for (int i = t; i < NSLOT; i += blockDim.x) {
        int e = ridx[i];
        int slot = soff[e] + atomicAdd(&cur[e], 1);
        d_slot_token[slot]  = i >> 1;
        d_slot_expert[slot] = e;
        d_slot_w[slot]      = rw[i];
    }
    if (t < E_) { d_count[t] = cnt[t]; d_off[t] = soff[t]; }
}

// ---------------- zero output (atomically accumulated later) -----------------
__global__ void zero_out_kernel(float* __restrict__ out) {
    int i = blockIdx.x * 256 + threadIdx.x;
    *(float4*)&out[(size_t)i * 4] = make_float4(0.f, 0.f, 0.f, 0.f);
}

// ---------------- LoRA rank projection --------------------------------------
// STAGE1: src row = x[token(slot)]; STAGE2: src row = d_g[slot]
template <bool STAGE1>
__global__ void lora_r_kernel(const float* __restrict__ xsrc,
                              const float* __restrict__ A) {  // [E,1024,16]
    int slot = blockIdx.x;
    int e    = d_slot_expert[slot];
    const float* Ae   = A + (size_t)e * 1024 * R_;
    const float* srow = STAGE1 ? (xsrc + (size_t)d_slot_token[slot] * 1024)
                               : (d_g + (size_t)slot * 1024);
    float* rout = STAGE1 ? d_r1 : d_r2;
    int tid = threadIdx.x;  // 256
    float acc[R_];
#pragma unroll
    for (int j = 0; j < R_; j++) acc[j] = 0.f;
    for (int k = tid; k < 1024; k += 256) {
        float a = srow[k];
        const float4* ar = (const float4*)(Ae + k * R_);
#pragma unroll
        for (int q = 0; q < 4; q++) {
            float4 v = __ldg(ar + q);
            acc[q * 4]     += a * v.x;
            acc[q * 4 + 1] += a * v.y;
            acc[q * 4 + 2] += a * v.z;
            acc[q * 4 + 3] += a * v.w;
        }
    }
#pragma unroll
    for (int o = 16; o > 0; o >>= 1)
#pragma unroll
        for (int j = 0; j < R_; j++)
            acc[j] += __shfl_down_sync(0xffffffffu, acc[j], o);
    __shared__ float wr[8][R_];
    int lane = tid & 31, w = tid >> 5;
    if (lane == 0)
#pragma unroll
        for (int j = 0; j < R_; j++) wr[w][j] = acc[j];
    __syncthreads();
    if (tid < R_) {
        float s = 0.f;
#pragma unroll
        for (int ww = 0; ww < 8; ww++) s += wr[ww][tid];
        rout[slot * R_ + tid] = s;  // SCALING = 16/16 = 1
    }
}

// ================= mma.sync helpers =========================================
__device__ __forceinline__ uint32_t smem_u32(const void* p) {
    return (uint32_t)__cvta_generic_to_shared(p);
}
__device__ __forceinline__ void ldsm4(uint32_t* r, uint32_t addr) {
    asm volatile("ldmatrix.sync.aligned.m8n8.x4.shared.b16 {%0,%1,%2,%3}, [%4];"
                 : "=r"(r[0]), "=r"(r[1]), "=r"(r[2]), "=r"(r[3]) : "r"(addr));
}
__device__ __forceinline__ void ldsm4t(uint32_t* r, uint32_t addr) {
    asm volatile("ldmatrix.sync.aligned.m8n8.x4.trans.shared.b16 {%0,%1,%2,%3}, [%4];"
                 : "=r"(r[0]), "=r"(r[1]), "=r"(r[2]), "=r"(r[3]) : "r"(addr));
}
__device__ __forceinline__ void mma16816f(float* d, const uint32_t* a,
                                          const uint32_t* b) {
    asm volatile(
        "mma.sync.aligned.m16n8k16.row.col.f32.f16.f16.f32 "
        "{%0,%1,%2,%3}, {%4,%5,%6,%7}, {%8,%9}, {%0,%1,%2,%3};"
        : "+f"(d[0]), "+f"(d[1]), "+f"(d[2]), "+f"(d[3])
        : "r"(a[0]), "r"(a[1]), "r"(a[2]), "r"(a[3]), "r"(b[0]), "r"(b[1]));
}
// pack 8 floats (two float4) -> 8 f16 in a uint4, via cvt.rn.f16x2.f32
__device__ __forceinline__ uint4 cvt8_f16(const float4 a, const float4 b) {
    uint4 r;
    asm("cvt.rn.f16x2.f32 %0, %1, %2;" : "=r"(r.x) : "f"(a.y), "f"(a.x));
    asm("cvt.rn.f16x2.f32 %0, %1, %2;" : "=r"(r.y) : "f"(a.w), "f"(a.z));
    asm("cvt.rn.f16x2.f32 %0, %1, %2;" : "=r"(r.z) : "f"(b.y), "f"(b.x));
    asm("cvt.rn.f16x2.f32 %0, %1, %2;" : "=r"(r.w) : "f"(b.w), "f"(b.z));
    return r;
}

// SMEM layout (static, 20480 B), double-buffered f16:
//   A[stage]: 128 rows x 48B (32B data + 16B pad)  @ s*6144
//   B[stage]: 16 k-rows x 256B (XOR-swizzled)      @ 12288 + s*4096
#define SM_A(s) ((s) * 6144)
#define SM_B(s) (12288 + (s) * 4096)

// ================= grouped GEMM via mma.sync fp16 ===========================
// STAGE1: d_g = act(x[tok] @ Wgu + r1 @ LBgu + bias)    Ncols=2048
// STAGE2: out += w * (d_g @ Wdn + r2 @ LBdn + bias)     Ncols=1024, atomics
// CTA tile 128x128, BK=16; K-loop: 64 main iters + 1 LoRA iter (rank 16).
template <bool STAGE1>
__global__ __launch_bounds__(256, 2)
void moe_mma_kernel(const float* __restrict__ xsrc,  // x (stage1) / unused
                    const float* __restrict__ W,     // [E,1024,Ncols]
                    const float* __restrict__ LB,    // [E,16,Ncols]
                    const float* __restrict__ bias,  // [E,Ncols]
                    float* __restrict__ Out,         // final out (stage2)
                    int Ncols) {
    const int e  = blockIdx.z;
    const int ne = d_count[e];
    const int off = d_off[e];
    const int n0  = blockIdx.x * 128;
    const float* Rsrc = STAGE1 ? d_r1 : d_r2;
    float* Outp = STAGE1 ? d_g : Out;

    __shared__ __align__(16) char sm[20480];
    const uint32_t sb = smem_u32(sm);

    const int tid  = threadIdx.x;
    const int lane = tid & 31;
    const int wid  = tid >> 5;
    const int wm   = wid >> 2;       // 0..1 (64 rows)
    const int wn   = wid & 3;        // 0..3 (32 cols)

    // fixed per-thread load mapping
    const int arow = tid >> 1;            // 0..127 (row; 2 threads/row)
    const int ac0  = (tid & 1) * 8;       // 8-float half of the 16-float k-chunk
    const int krow = tid >> 4;            // 0..15
    const int bc   = tid & 15;            // 16B chunk within 256B row
    const int bofs_sw = krow * 256 + ((bc ^ (krow & 7)) << 4);
    const float* bptr  = W  + ((size_t)e * 1024 + krow) * Ncols + n0 + bc * 8;
    const float* lbptr = LB + ((size_t)e * R_   + krow) * Ncols + n0 + bc * 8;

    for (int mb = blockIdx.y; mb * 128 < ne; mb += 4) {
        const int m0 = mb * 128;
        const bool avalid = (m0 + arow) < ne;
        const int aslot = off + m0 + arow;
        const float* aptr = nullptr;
        const float* rptr = nullptr;
        if (avalid) {
            aptr = STAGE1 ? (xsrc + (size_t)d_slot_token[aslot] * 1024)
                          : (d_g + (size_t)aslot * 1024);
            rptr = Rsrc + (size_t)aslot * R_;
        }

        float acc[4][4][4];
#pragma unroll
        for (int i = 0; i < 4; i++)
#pragma unroll
            for (int j = 0; j < 4; j++)
#pragma unroll
                for (int q = 0; q < 4; q++) acc[i][j][q] = 0.f;

        float4 pa0, pa1, pb0, pb1;
        auto loadtile = [&](int it) {
            if (it < 64) {
                if (avalid) {
                    pa0 = __ldg((const float4*)(aptr + it * 16 + ac0));
                    pa1 = __ldg((const float4*)(aptr + it * 16 + ac0 + 4));
                } else { pa0 = pa1 = make_float4(0.f, 0.f, 0.f, 0.f); }
                pb0 = __ldg((const float4*)(bptr + (size_t)it * 16 * Ncols));
                pb1 = __ldg((const float4*)(bptr + (size_t)it * 16 * Ncols + 4));
            } else {
                if (avalid) {
                    pa0 = __ldg((const float4*)(rptr + ac0));
                    pa1 = __ldg((const float4*)(rptr + ac0 + 4));
                } else { pa0 = pa1 = make_float4(0.f, 0.f, 0.f, 0.f); }
                pb0 = __ldg((const float4*)lbptr);
                pb1 = __ldg((const float4*)(lbptr + 4));
            }
        };
        auto storetile = [&](int s) {
            *(uint4*)(sm + SM_A(s) + arow * 48 + (tid & 1) * 16) = cvt8_f16(pa0, pa1);
            *(uint4*)(sm + SM_B(s) + bofs_sw) = cvt8_f16(pb0, pb1);
        };

        loadtile(0);
        storetile(0);
        __syncthreads();
        int s = 0;
        for (int it = 0; it <= 64; ++it) {
            if (it < 64) loadtile(it + 1);   // prefetch (hidden under MMAs)

            // ---- B fragments: 2x ldmatrix.x4.trans (16 n-cols each) ----
            uint32_t bh[2][4];
            {
                int k = ((lane >> 3) & 1) * 8 + (lane & 7);
                int cbase = (lane >> 4);
#pragma unroll
                for (int g = 0; g < 2; g++) {
                    int c = wn * 4 + g * 2 + cbase;
                    ldsm4t(bh[g], sb + SM_B(s) + k * 256 + ((c ^ (k & 7)) << 4));
                }
            }
            // ---- A fragments + MMAs ----
#pragma unroll
            for (int mt = 0; mt < 4; mt++) {
                uint32_t ah[4];
                int m = wm * 64 + mt * 16 + (lane & 15);
                ldsm4(ah, sb + SM_A(s) + m * 48 + (lane >> 4) * 16);
#pragma unroll
                for (int nt = 0; nt < 4; nt++)
                    mma16816f(acc[mt][nt], ah, &bh[nt >> 1][(nt & 1) * 2]);
            }
            if (it < 64) storetile(s ^ 1);
            __syncthreads();
            s ^= 1;
        }

        // ---- epilogue ----
        const float* be = bias + (size_t)e * Ncols + n0;
        float bb[4][2];
#pragma unroll
        for (int nt = 0; nt < 4; nt++) {
            int col = wn * 32 + nt * 8 + (lane & 3) * 2;
            bb[nt][0] = __ldg(be + col);
            bb[nt][1] = __ldg(be + col + 1);
        }
#pragma unroll
        for (int mt = 0; mt < 4; mt++) {
            int rbase = m0 + wm * 64 + mt * 16 + (lane >> 2);
#pragma unroll
            for (int half = 0; half < 2; half++) {
                int r = rbase + half * 8;
                if (r >= ne) continue;
                int slot = off + r;
                if (STAGE1) {
                    size_t orow = (size_t)slot * 1024 + (n0 >> 1);
#pragma unroll
                    for (int nt = 0; nt < 4; nt++) {
                        float c0 = acc[mt][nt][half * 2]     + bb[nt][0];
                        float c1 = acc[mt][nt][half * 2 + 1] + bb[nt][1];
                        int col = wn * 32 + nt * 8 + (lane & 3) * 2;
                        float gate = fminf(c0, LIMIT_);
                        float up   = fminf(fmaxf(c1, -LIMIT_), LIMIT_);
                        float glu  = gate / (1.f + expf(-ACT_ALPHA_ * gate));
                        Outp[orow + (col >> 1)] = (up + 1.f) * glu;
                    }
                } else {
                    float wgt = d_slot_w[slot];
                    size_t orow = (size_t)d_slot_token[slot] * 1024 + n0;
#pragma unroll
                    for (int nt = 0; nt < 4; nt++) {
                        float c0 = acc[mt][nt][half * 2]     + bb[nt][0];
                        float c1 = acc[mt][nt][half * 2 + 1] + bb[nt][1];
                        int col = wn * 32 + nt * 8 + (lane & 3) * 2;
                        atomicAdd(Outp + orow + col,     wgt * c0);
                        atomicAdd(Outp + orow + col + 1, wgt * c1);
                    }
                }
            }
        }
        __syncthreads();  // smem safe for next m-block
    }
}

// ---------------- launch: kernel launches ONLY ------------------------------
extern "C" void kernel_launch(void* const* d_in, const int* in_sizes, int n_in,
                              void* d_out, int out_size) {
    const float* x     = (const float*)d_in[0];
    const int*   ridx  = (const int*)  d_in[1];
    const float* rw    = (const float*)d_in[2];
    const float* w_gu  = (const float*)d_in[3];
    const float* b_gu  = (const float*)d_in[4];
    const float* w_dn  = (const float*)d_in[5];
    const float* b_dn  = (const float*)d_in[6];
    const float* la_gu = (const float*)d_in[7];
    const float* lb_gu = (const float*)d_in[8];
    const float* la_dn = (const float*)d_in[9];
    const float* lb_dn = (const float*)d_in[10];
    float* out = (float*)d_out;

    route_kernel<<<1, 1024>>>(ridx, rw);
    zero_out_kernel<<<T_ * H_ / 1024, 256>>>(out);

    lora_r_kernel<true ><<<NSLOT, 256>>>(x, la_gu);
    moe_mma_kernel<true ><<<dim3(D_ / 128, 4, E_), 256>>>(x, w_gu, lb_gu, b_gu,
                                                          nullptr, D_);
    lora_r_kernel<false><<<NSLOT, 256>>>(x, la_dn);
    moe_mma_kernel<false><<<dim3(H_ / 128, 4, E_), 256>>>(x, w_dn, lb_dn, b_dn,
                                                          out, H_);
}